// round 1
// baseline (speedup 1.0000x reference)
#include <cuda_runtime.h>
#include <math.h>

#define BB   8
#define LL   2016
#define HH   4
#define DKK  32
#define DD   256
#define FCC  64
#define NLL  3
#define BL   (BB*LL)      // 16128
#define HD   (HH*DKK)     // 128
#define SCALE 0.0625f     // 1/sqrt(256)
#define EPSV  1e-5f

// ---------------- scratch (device globals: no allocation allowed) ----------
__device__ float g_h [BL*DD];
__device__ float g_q [BL*HD];
__device__ float g_k [BL*HD];
__device__ float g_v [BL*HD];
__device__ float g_o [BL*HD];
__device__ float g_t1[BL*DD];
__device__ float g_ff[BL*FCC];

// ---------------- input projection: h = x @ in_w + in_b (K=2) -------------
__global__ void k_input(const float* __restrict__ x, const float* __restrict__ w,
                        const float* __restrict__ b, float* __restrict__ h) {
    int idx = blockIdx.x * 256 + threadIdx.x;       // over BL*DD
    int d = idx & (DD - 1);
    int r = idx >> 8;
    h[idx] = fmaf(x[2*r], w[d], fmaf(x[2*r+1], w[DD + d], b[d]));
}

// ---------------- generic fp32 GEMM: C = A(MxK) @ W(KxN) + bias [, relu] ---
// M % 64 == 0, N % 64 == 0, K % 16 == 0  (all call sites satisfy this)
template<bool RELU>
__global__ void k_gemm(const float* __restrict__ A, const float* __restrict__ W,
                       const float* __restrict__ bias, float* __restrict__ C,
                       int M, int N, int K) {
    __shared__ float As[16][65];
    __shared__ float Ws[16][64];
    int tid = threadIdx.x;
    int tx = tid & 15, ty = tid >> 4;
    int m0 = blockIdx.y * 64, n0 = blockIdx.x * 64;
    float acc[4][4] = {};
    for (int k0 = 0; k0 < K; k0 += 16) {
        for (int idx = tid; idx < 1024; idx += 256) {
            int m = idx >> 4, k = idx & 15;
            As[k][m] = A[(size_t)(m0 + m) * K + k0 + k];
        }
        for (int idx = tid; idx < 1024; idx += 256) {
            int k = idx >> 6, n = idx & 63;
            Ws[k][n] = W[(size_t)(k0 + k) * N + n0 + n];
        }
        __syncthreads();
        #pragma unroll
        for (int k = 0; k < 16; k++) {
            float a[4], bv[4];
            #pragma unroll
            for (int i = 0; i < 4; i++) a[i]  = As[k][ty*4 + i];
            #pragma unroll
            for (int j = 0; j < 4; j++) bv[j] = Ws[k][tx*4 + j];
            #pragma unroll
            for (int i = 0; i < 4; i++)
                #pragma unroll
                for (int j = 0; j < 4; j++)
                    acc[i][j] = fmaf(a[i], bv[j], acc[i][j]);
        }
        __syncthreads();
    }
    #pragma unroll
    for (int i = 0; i < 4; i++) {
        int m = m0 + ty*4 + i;
        #pragma unroll
        for (int j = 0; j < 4; j++) {
            int n = n0 + tx*4 + j;
            float c = acc[i][j] + bias[n];
            if (RELU) c = fmaxf(c, 0.f);
            C[(size_t)m * N + n] = c;
        }
    }
}

// ---------------- scores: S[bh,l,s] = scale * <Q[b,l,h,:], K[b,s,h,:]> -----
__global__ void k_scores(const float* __restrict__ Q, const float* __restrict__ Kv,
                         float* __restrict__ S) {
    __shared__ float Qs[32][65];
    __shared__ float Ks[32][65];
    int tid = threadIdx.x;
    int tx = tid & 15, ty = tid >> 4;
    int l0 = blockIdx.y * 64, s0 = blockIdx.x * 64;
    int bh = blockIdx.z; int b = bh >> 2, hh = bh & 3;
    const float* qb = Q  + (size_t)b * LL * HD + hh * DKK;
    const float* kb = Kv + (size_t)b * LL * HD + hh * DKK;
    for (int idx = tid; idx < 2048; idx += 256) {
        int l = idx >> 5, e = idx & 31;
        Qs[e][l] = (l0 + l < LL) ? qb[(size_t)(l0 + l) * HD + e] : 0.f;
        Ks[e][l] = (s0 + l < LL) ? kb[(size_t)(s0 + l) * HD + e] : 0.f;
    }
    __syncthreads();
    float acc[4][4] = {};
    #pragma unroll
    for (int e = 0; e < 32; e++) {
        float a[4], bv[4];
        #pragma unroll
        for (int i = 0; i < 4; i++) a[i]  = Qs[e][ty*4 + i];
        #pragma unroll
        for (int j = 0; j < 4; j++) bv[j] = Ks[e][tx*4 + j];
        #pragma unroll
        for (int i = 0; i < 4; i++)
            #pragma unroll
            for (int j = 0; j < 4; j++)
                acc[i][j] = fmaf(a[i], bv[j], acc[i][j]);
    }
    float* Sb = S + (size_t)bh * LL * LL;
    #pragma unroll
    for (int i = 0; i < 4; i++) {
        int l = l0 + ty*4 + i;
        if (l >= LL) continue;
        #pragma unroll
        for (int j = 0; j < 4; j++) {
            int s = s0 + tx*4 + j;
            if (s < LL) Sb[(size_t)l * LL + s] = acc[i][j] * SCALE;
        }
    }
}

// ---------------- stable row softmax, in place (row length LL) -------------
__global__ void k_softmax(float* __restrict__ S) {
    __shared__ float red[256];
    float* p = S + (size_t)blockIdx.x * LL;
    int tid = threadIdx.x;
    float vals[8];
    float m = -1e30f;
    #pragma unroll
    for (int i = 0; i < 8; i++) {
        int idx = tid + i * 256;
        vals[i] = (idx < LL) ? p[idx] : -1e30f;
        m = fmaxf(m, vals[i]);
    }
    red[tid] = m; __syncthreads();
    for (int s = 128; s > 0; s >>= 1) {
        if (tid < s) red[tid] = fmaxf(red[tid], red[tid + s]);
        __syncthreads();
    }
    m = red[0]; __syncthreads();
    float sum = 0.f;
    #pragma unroll
    for (int i = 0; i < 8; i++) { vals[i] = __expf(vals[i] - m); sum += vals[i]; }
    red[tid] = sum; __syncthreads();
    for (int s = 128; s > 0; s >>= 1) {
        if (tid < s) red[tid] += red[tid + s];
        __syncthreads();
    }
    float inv = 1.f / red[0];
    #pragma unroll
    for (int i = 0; i < 8; i++) {
        int idx = tid + i * 256;
        if (idx < LL) p[idx] = vals[i] * inv;
    }
}

// ---------------- O[b,l,h,:] = sum_s P[bh,l,s] * V[b,s,h,:] ----------------
__global__ void k_pv(const float* __restrict__ S, const float* __restrict__ V,
                     float* __restrict__ O) {
    __shared__ float Ps[64][65];
    __shared__ float Vs[64][33];
    int tid = threadIdx.x;
    int l0 = blockIdx.x * 64;
    int bh = blockIdx.y; int b = bh >> 2, hh = bh & 3;
    const float* Sb = S + (size_t)bh * LL * LL;
    const float* vb = V + (size_t)b * LL * HD + hh * DKK;
    int rg = tid >> 4;       // row group: rows rg*4 .. rg*4+3
    int cg = tid & 15;       // col group: dv = cg*2, cg*2+1
    float acc[4][2] = {};
    for (int s0 = 0; s0 < LL; s0 += 64) {
        for (int idx = tid; idx < 4096; idx += 256) {
            int l = idx >> 6, s = idx & 63;
            Ps[l][s] = (l0 + l < LL && s0 + s < LL)
                     ? Sb[(size_t)(l0 + l) * LL + s0 + s] : 0.f;
        }
        for (int idx = tid; idx < 2048; idx += 256) {
            int s = idx >> 5, dv = idx & 31;
            Vs[s][dv] = (s0 + s < LL) ? vb[(size_t)(s0 + s) * HD + dv] : 0.f;
        }
        __syncthreads();
        #pragma unroll 8
        for (int s = 0; s < 64; s++) {
            float v0 = Vs[s][cg*2], v1 = Vs[s][cg*2 + 1];
            #pragma unroll
            for (int i = 0; i < 4; i++) {
                float pp = Ps[rg*4 + i][s];
                acc[i][0] = fmaf(pp, v0, acc[i][0]);
                acc[i][1] = fmaf(pp, v1, acc[i][1]);
            }
        }
        __syncthreads();
    }
    float* ob = O + (size_t)b * LL * HD + hh * DKK;
    #pragma unroll
    for (int i = 0; i < 4; i++) {
        int l = l0 + rg*4 + i;
        if (l < LL) {
            ob[(size_t)l * HD + cg*2]     = acc[i][0];
            ob[(size_t)l * HD + cg*2 + 1] = acc[i][1];
        }
    }
}

// ---------------- h = LayerNorm(h + add) * g + b (row of 256) --------------
__global__ void k_ln(float* __restrict__ h, const float* __restrict__ add,
                     const float* __restrict__ g, const float* __restrict__ bta) {
    int row  = blockIdx.x * 8 + (threadIdx.x >> 5);
    int lane = threadIdx.x & 31;
    float* hp = h + (size_t)row * DD;
    const float* ap = add + (size_t)row * DD;
    float v[8]; float s = 0.f;
    #pragma unroll
    for (int i = 0; i < 8; i++) {
        v[i] = hp[lane + 32*i] + ap[lane + 32*i];
        s += v[i];
    }
    #pragma unroll
    for (int o = 16; o > 0; o >>= 1) s += __shfl_xor_sync(0xffffffffu, s, o);
    float mean = s * (1.f / DD);
    float var = 0.f;
    #pragma unroll
    for (int i = 0; i < 8; i++) { float d = v[i] - mean; var = fmaf(d, d, var); }
    #pragma unroll
    for (int o = 16; o > 0; o >>= 1) var += __shfl_xor_sync(0xffffffffu, var, o);
    var *= (1.f / DD);
    float r = rsqrtf(var + EPSV);
    #pragma unroll
    for (int i = 0; i < 8; i++) {
        int d = lane + 32*i;
        hp[d] = (v[i] - mean) * r * g[d] + bta[d];
    }
}

// ---------------- final head: out = A(relu'd) @ o2w(256x2) + o2b -----------
__global__ void k_out2(const float* __restrict__ A, const float* __restrict__ w,
                       const float* __restrict__ b, float* __restrict__ out) {
    int row  = blockIdx.x * 8 + (threadIdx.x >> 5);
    int lane = threadIdx.x & 31;
    const float* ap = A + (size_t)row * DD;
    float s0 = 0.f, s1 = 0.f;
    #pragma unroll
    for (int i = 0; i < 8; i++) {
        int d = lane + 32*i;
        float a = ap[d];
        s0 = fmaf(a, w[d*2],     s0);
        s1 = fmaf(a, w[d*2 + 1], s1);
    }
    #pragma unroll
    for (int o = 16; o > 0; o >>= 1) {
        s0 += __shfl_xor_sync(0xffffffffu, s0, o);
        s1 += __shfl_xor_sync(0xffffffffu, s1, o);
    }
    if (lane == 0) {
        out[(size_t)row*2]     = s0 + b[0];
        out[(size_t)row*2 + 1] = s1 + b[1];
    }
}

// ---------------------------------------------------------------------------
extern "C" void kernel_launch(void* const* d_in, const int* in_sizes, int n_in,
                              void* d_out, int out_size) {
    const float* x    = (const float*)d_in[0];
    const float* in_w = (const float*)d_in[1];
    const float* in_b = (const float*)d_in[2];
    const float* qw   = (const float*)d_in[3];
    const float* qb   = (const float*)d_in[4];
    const float* kw   = (const float*)d_in[5];
    const float* kb   = (const float*)d_in[6];
    const float* vw   = (const float*)d_in[7];
    const float* vb   = (const float*)d_in[8];
    const float* ow   = (const float*)d_in[9];
    const float* ob   = (const float*)d_in[10];
    const float* f1w  = (const float*)d_in[11];
    const float* f1b  = (const float*)d_in[12];
    const float* f2w  = (const float*)d_in[13];
    const float* f2b  = (const float*)d_in[14];
    const float* n1g  = (const float*)d_in[15];
    const float* n1b  = (const float*)d_in[16];
    const float* n2g  = (const float*)d_in[17];
    const float* n2b  = (const float*)d_in[18];
    const float* o1w  = (const float*)d_in[19];
    const float* o1b  = (const float*)d_in[20];
    const float* o2w  = (const float*)d_in[21];
    const float* o2b  = (const float*)d_in[22];

    float* out  = (float*)d_out;
    float* attn = out + (size_t)BB * LL * 2;   // attns region: (NL,B,H,L,L)

    float *h, *q, *k, *v, *o, *t1, *ff;
    cudaGetSymbolAddress((void**)&h,  g_h);
    cudaGetSymbolAddress((void**)&q,  g_q);
    cudaGetSymbolAddress((void**)&k,  g_k);
    cudaGetSymbolAddress((void**)&v,  g_v);
    cudaGetSymbolAddress((void**)&o,  g_o);
    cudaGetSymbolAddress((void**)&t1, g_t1);
    cudaGetSymbolAddress((void**)&ff, g_ff);

    // input projection
    k_input<<<(BL*DD)/256, 256>>>(x, in_w, in_b, h);

    const int LT = (LL + 63) / 64;   // 32 tiles

    for (int i = 0; i < NLL; i++) {
        const float* qwi = qw + (size_t)i * DD * HD;
        const float* qbi = qb + (size_t)i * HD;
        const float* kwi = kw + (size_t)i * DD * HD;
        const float* kbi = kb + (size_t)i * HD;
        const float* vwi = vw + (size_t)i * DD * HD;
        const float* vbi = vb + (size_t)i * HD;
        const float* owi = ow + (size_t)i * HD * DD;
        const float* obi = ob + (size_t)i * DD;
        const float* f1wi = f1w + (size_t)i * DD * FCC;
        const float* f1bi = f1b + (size_t)i * FCC;
        const float* f2wi = f2w + (size_t)i * FCC * DD;
        const float* f2bi = f2b + (size_t)i * DD;

        // Q,K,V projections
        k_gemm<false><<<dim3(HD/64, BL/64), 256>>>(h, qwi, qbi, q, BL, HD, DD);
        k_gemm<false><<<dim3(HD/64, BL/64), 256>>>(h, kwi, kbi, k, BL, HD, DD);
        k_gemm<false><<<dim3(HD/64, BL/64), 256>>>(h, vwi, vbi, v, BL, HD, DD);

        float* Si = attn + (size_t)i * BB * HH * LL * LL;
        k_scores<<<dim3(LT, LT, BB*HH), 256>>>(q, k, Si);
        k_softmax<<<BB*HH*LL, 256>>>(Si);
        k_pv<<<dim3(LT, BB*HH), 256>>>(Si, v, o);

        // output projection + residual LN
        k_gemm<false><<<dim3(DD/64, BL/64), 256>>>(o, owi, obi, t1, BL, DD, HD);
        k_ln<<<BL/8, 256>>>(h, t1, n1g + (size_t)i*DD, n1b + (size_t)i*DD);

        // FFN + residual LN
        k_gemm<true ><<<dim3(FCC/64, BL/64), 256>>>(h, f1wi, f1bi, ff, BL, FCC, DD);
        k_gemm<false><<<dim3(DD/64, BL/64), 256>>>(ff, f2wi, f2bi, t1, BL, DD, FCC);
        k_ln<<<BL/8, 256>>>(h, t1, n2g + (size_t)i*DD, n2b + (size_t)i*DD);
    }

    // final MLP head
    k_gemm<true><<<dim3(DD/64, BL/64), 256>>>(h, o1w, o1b, t1, BL, DD, DD);
    k_out2<<<BL/8, 256>>>(t1, o2w, o2b, out);
}